// round 16
// baseline (speedup 1.0000x reference)
#include <cuda_runtime.h>
#include <cuda_fp16.h>
#include <math.h>
#include <stdint.h>

#define BB 64
#define TT 256
#define IIN 1024
#define HHID 512

// ---------------- device scratch (static: no allocations allowed) ----------------
__device__ __half d_xh[16384u * 1024u];
__device__ __half d_wih1[1536u * 1024u];
__device__ __half d_whh1[1536u * 512u];
__device__ __half d_wih2[3072u * 512u];
__device__ __half d_whh2[3072u * 1024u];
__device__ float  d_gx1[16384u * 1536u];
__device__ float  d_gx2[16384u * 3072u];
__device__ __half d_hbuf16[2][64 * 1024];
// Barrier counters: one padded 128B line per group.
__device__ unsigned int d_bar1[4 * 32];
__device__ unsigned int d_bar2[4 * 32];

// ---------------- helpers ----------------
__device__ __forceinline__ uint32_t ld32h(const __half* p) {
    return *reinterpret_cast<const uint32_t*>(p);
}

__device__ __forceinline__ void mma16816(float* c, const uint32_t* a, const uint32_t* b) {
    asm volatile(
        "mma.sync.aligned.m16n8k16.row.col.f32.f16.f16.f32 "
        "{%0,%1,%2,%3}, {%4,%5,%6,%7}, {%8,%9}, {%0,%1,%2,%3};\n"
        : "+f"(c[0]), "+f"(c[1]), "+f"(c[2]), "+f"(c[3])
        : "r"(a[0]), "r"(a[1]), "r"(a[2]), "r"(a[3]), "r"(b[0]), "r"(b[1]));
}

__device__ __forceinline__ void ldsm_x4(uint32_t* r, const __half* p) {
    unsigned sa = (unsigned)__cvta_generic_to_shared(p);
    asm volatile("ldmatrix.sync.aligned.m8n8.x4.shared.b16 {%0,%1,%2,%3}, [%4];\n"
                 : "=r"(r[0]), "=r"(r[1]), "=r"(r[2]), "=r"(r[3]) : "r"(sa));
}

__device__ __forceinline__ uint32_t relu_h2(uint32_t x) {
    uint32_t r;
    asm("max.f16x2 %0, %1, %2;\n" : "=r"(r) : "r"(x), "r"(0u));
    return r;
}

__device__ __forceinline__ float tanh_hw(float x) {
    float y;
    asm("tanh.approx.f32 %0, %1;\n" : "=f"(y) : "f"(x));
    return y;
}
__device__ __forceinline__ void sigm2_hw(float x0, float x1, float& s0, float& s1) {
    __half2 hin = __floats2half2_rn(0.5f * x0, 0.5f * x1);
    uint32_t uin = *reinterpret_cast<uint32_t*>(&hin);
    uint32_t uout;
    asm("tanh.approx.f16x2 %0, %1;\n" : "=r"(uout) : "r"(uin));
    __half2 hout = *reinterpret_cast<__half2*>(&uout);
    float2 t = __half22float2(hout);
    s0 = fmaf(t.x, 0.5f, 0.5f);
    s1 = fmaf(t.y, 0.5f, 0.5f);
}

__device__ __forceinline__ void cp16(void* s, const void* g) {
    unsigned sa = (unsigned)__cvta_generic_to_shared(s);
    asm volatile("cp.async.cg.shared.global [%0], [%1], 16;\n" :: "r"(sa), "l"(g));
}
__device__ __forceinline__ void cp_commit() { asm volatile("cp.async.commit_group;\n"); }
__device__ __forceinline__ void cp_wait0()  { asm volatile("cp.async.wait_group 0;\n"); }
__device__ __forceinline__ void cp_wait_dyn(int n) {
    switch (n) {
        case 0: asm volatile("cp.async.wait_group 0;\n"); break;
        case 1: asm volatile("cp.async.wait_group 1;\n"); break;
        case 2: asm volatile("cp.async.wait_group 2;\n"); break;
        default: asm volatile("cp.async.wait_group 3;\n"); break;
    }
}

// Split grid barrier (single padded counter per group).
__device__ __forceinline__ void bar_arrive(unsigned int* ctr) {
    __syncthreads();
    if (threadIdx.x == 0) {
        asm volatile("red.release.gpu.global.add.u32 [%0], 1;\n" :: "l"(ctr) : "memory");
    }
}
__device__ __forceinline__ void bar_wait(unsigned int* ctr, unsigned int target) {
    if (threadIdx.x == 0) {
        unsigned int v;
        do {
            asm volatile("ld.acquire.gpu.global.u32 %0, [%1];\n" : "=r"(v) : "l"(ctr) : "memory");
        } while (v < target);
    }
    __syncthreads();
}

// ---------------- prep ----------------
__global__ void prep_kernel(const float* __restrict__ x,
                            const float* __restrict__ wih1, const float* __restrict__ whh1,
                            const float* __restrict__ wih2, const float* __restrict__ whh2) {
    long idx = (long)blockIdx.x * blockDim.x + threadIdx.x;
    long stride = (long)gridDim.x * blockDim.x;
    if (idx < 4 * 32) { d_bar1[idx] = 0u; d_bar2[idx] = 0u; }
    for (long i = idx; i < 16384L * 1024L; i += stride) d_xh[i]   = __float2half(x[i]);
    for (long i = idx; i < 1536L * 1024L;  i += stride) d_wih1[i] = __float2half(wih1[i]);
    for (long i = idx; i < 1536L * 512L;   i += stride) d_whh1[i] = __float2half(whh1[i]);
    for (long i = idx; i < 3072L * 512L;   i += stride) d_wih2[i] = __float2half(wih2[i]);
    for (long i = idx; i < 3072L * 1024L;  i += stride) d_whh2[i] = __float2half(whh2[i]);
}

// ---------------- 2-stage pipelined SMEM GEMM, A+B frags via ldmatrix (R15 proven) ----------------
#define SSTR 40
__global__ __launch_bounds__(256) void gemm_tn_kernel(
        const __half* __restrict__ A, const __half* __restrict__ W,
        const float* __restrict__ bias, float* __restrict__ C,
        int M, int N, int K) {
    __shared__ __half sA[2][128 * SSTR];
    __shared__ __half sB[2][128 * SSTR];

    const int bn = blockIdx.x * 128;
    const int bm = blockIdx.y * 128;
    const int tid = threadIdx.x;
    const int w = tid >> 5, lane = tid & 31;
    const int g = lane >> 2, tg = lane & 3;
    const int wm = (w >> 2) * 64;
    const int wn = (w & 3) * 32;
    const int lr = lane & 15, lc = (lane >> 4) << 3;

    float acc[4][4][4];
#pragma unroll
    for (int mt = 0; mt < 4; mt++)
#pragma unroll
        for (int nt = 0; nt < 4; nt++)
#pragma unroll
            for (int e = 0; e < 4; e++) acc[mt][nt][e] = 0.0f;

    const int KT = K >> 5;
    {
#pragma unroll
        for (int c = 0; c < 2; c++) {
            int chunk = tid + c * 256;
            int r = chunk >> 2, cc = chunk & 3;
            cp16(&sA[0][r * SSTR + cc * 8], A + (long)(bm + r) * K + cc * 8);
            cp16(&sB[0][r * SSTR + cc * 8], W + (long)(bn + r) * K + cc * 8);
        }
        cp_commit();
    }

    for (int kt = 0; kt < KT; kt++) {
        cp_wait0();
        __syncthreads();
        if (kt + 1 < KT) {
            int k0 = (kt + 1) << 5;
            int nb = (kt + 1) & 1;
#pragma unroll
            for (int c = 0; c < 2; c++) {
                int chunk = tid + c * 256;
                int r = chunk >> 2, cc = chunk & 3;
                cp16(&sA[nb][r * SSTR + cc * 8], A + (long)(bm + r) * K + k0 + cc * 8);
                cp16(&sB[nb][r * SSTR + cc * 8], W + (long)(bn + r) * K + k0 + cc * 8);
            }
            cp_commit();
        }
        const __half* a_s = sA[kt & 1];
        const __half* b_s = sB[kt & 1];
#pragma unroll
        for (int ks = 0; ks < 2; ks++) {
            const int kk = ks * 16;
            uint32_t af[4][4];
#pragma unroll
            for (int mt = 0; mt < 4; mt++) {
                ldsm_x4(af[mt], a_s + (wm + mt * 16 + lr) * SSTR + kk + lc);
            }
            uint32_t bm4[2][4];
#pragma unroll
            for (int h = 0; h < 2; h++) {
                ldsm_x4(bm4[h], b_s + (wn + h * 16 + lr) * SSTR + kk + lc);
            }
            uint32_t bf[4][2];
#pragma unroll
            for (int h = 0; h < 2; h++) {
                bf[h * 2][0]     = bm4[h][0];
                bf[h * 2][1]     = bm4[h][2];
                bf[h * 2 + 1][0] = bm4[h][1];
                bf[h * 2 + 1][1] = bm4[h][3];
            }
#pragma unroll
            for (int mt = 0; mt < 4; mt++)
#pragma unroll
                for (int nt = 0; nt < 4; nt++) mma16816(acc[mt][nt], af[mt], bf[nt]);
        }
    }

#pragma unroll
    for (int mt = 0; mt < 4; mt++) {
        int row0 = bm + wm + mt * 16 + g;
#pragma unroll
        for (int nt = 0; nt < 4; nt++) {
            int col = bn + wn + nt * 8 + tg * 2;
            float b0 = bias[col], b1 = bias[col + 1];
            float2 v0 = make_float2(acc[mt][nt][0] + b0, acc[mt][nt][1] + b1);
            float2 v1 = make_float2(acc[mt][nt][2] + b0, acc[mt][nt][3] + b1);
            *reinterpret_cast<float2*>(&C[(long)row0 * N + col])       = v0;
            *reinterpret_cast<float2*>(&C[(long)(row0 + 8) * N + col]) = v1;
        }
    }
}

// gx2 slice from sH (raw h1 in fp16; relu applied in-register).
template <int STRIDE>
__device__ __forceinline__ void gx2_slice(const __half* sH, const uint32_t* sW2,
                                          float* gx2out, const float* bih2,
                                          int row0, int j96, int t, int w, int lane) {
    const int g = lane >> 2, tg = lane & 3;
    const int lr = lane & 15, lc = (lane >> 4) << 3;
    float acc2[2][4];
#pragma unroll
    for (int rep = 0; rep < 2; rep++)
#pragma unroll
        for (int e = 0; e < 4; e++) acc2[rep][e] = 0.0f;
#pragma unroll
    for (int ki = 0; ki < 32; ki++) {
        uint32_t a[4];
        ldsm_x4(a, sH + lr * STRIDE + ki * 16 + lc);
#pragma unroll
        for (int q = 0; q < 4; q++) a[q] = relu_h2(a[q]);
#pragma unroll
        for (int rep = 0; rep < 2; rep++) {
            if (rep == 0 || w < 4) {
                int nt = w + rep * 8;
                int base2 = ((ki * 12 + nt) * 32 + lane) * 2;
                uint2 bp = *reinterpret_cast<const uint2*>(&sW2[base2]);
                uint32_t b[2] = { bp.x, bp.y };
                mma16816(acc2[rep], a, b);
            }
        }
    }
#pragma unroll
    for (int rep = 0; rep < 2; rep++) {
        if (rep == 0 || w < 4) {
            int nt = w + rep * 8;
            int col = j96 + nt * 8 + tg * 2;
            float bi0 = bih2[col], bi1 = bih2[col + 1];
            long o0 = ((long)(row0 + g) * TT + t) * 3072 + col;
            long o1 = ((long)(row0 + g + 8) * TT + t) * 3072 + col;
            *reinterpret_cast<float2*>(&gx2out[o0]) = make_float2(acc2[rep][0] + bi0, acc2[rep][1] + bi1);
            *reinterpret_cast<float2*>(&gx2out[o1]) = make_float2(acc2[rep][2] + bi0, acc2[rep][3] + bi1);
        }
    }
}

// ---------------- persistent GRU recurrence, GPC groups interleaved per CTA ----------------
// ROWS=16 per group; KSPLIT=8 (all 8 warps K-split, single M-tile). Each CTA owns 16
// j-columns for GPC batch-groups and alternates per-group phases; one group's barrier
// settle + h L2 latency is hidden by the other group's compute.
template <int H, int LAYER, int KSPLIT, int GROUPS, int NSPLIT, int GPC>
__global__ __launch_bounds__(256) void rec_kernel(
        const float* __restrict__ gx, const __half* __restrict__ whh,
        const float* __restrict__ bhh, float* __restrict__ outp,
        unsigned int* __restrict__ barctr,
        const __half* __restrict__ wih2s, const float* __restrict__ bih2,
        float* __restrict__ gx2out) {
    constexpr int ROWS = 16;
    constexpr int K = H;
    constexpr int Kw = K / KSPLIT;
    constexpr int KI = Kw / 16;
    constexpr int CJ = H / 16;
    constexpr int GA = 3 * H;
    constexpr int STRIDE = H + 8;
    constexpr int PAIRS = ROWS * 8;            // 128 active gate threads
    constexpr int PARTW = Kw / NSPLIT;
    constexpr int CPR = PARTW / 8;
    constexpr int ITER = (16 * CPR) / 32;
    constexpr int KIP = KI / NSPLIT;
    constexpr int NPAIR = GROUPS / GPC;

    extern __shared__ unsigned char smem[];
    __half*   sH   = reinterpret_cast<__half*>(smem);
    uint32_t* sB   = reinterpret_cast<uint32_t*>(smem + (size_t)ROWS * STRIDE * 2);
    float*    sRed = reinterpret_cast<float*>(smem + (size_t)ROWS * STRIDE * 2 + (size_t)KSPLIT * KI * 6 * 64 * 4);
    uint32_t* sW2  = reinterpret_cast<uint32_t*>(smem + (size_t)ROWS * STRIDE * 2 + (size_t)KSPLIT * KI * 6 * 64 * 4
                                                 + (size_t)KSPLIT * ROWS * 48 * 4);

    const int tid = threadIdx.x;
    const int w = tid >> 5, lane = tid & 31;
    const int km = w % KSPLIT;                 // KSPLIT==8 -> km==w, single M-tile
    const int g = lane >> 2, tg = lane & 3;
    const int gpair = blockIdx.x % NPAIR;
    const int cidx = blockIdx.x / NPAIR;
    const int j0 = cidx * 16;
    const int j96 = cidx * 96;
    const int lr = lane & 15, lc = (lane >> 4) << 3;

    int row0s[GPC];
    unsigned int* ctrs[GPC];
#pragma unroll
    for (int s = 0; s < GPC; s++) {
        int grp = gpair * GPC + s;
        row0s[s] = grp * ROWS;
        ctrs[s] = barctr + grp * 32;
    }

    // Stage W_hh fragments once (all warps; km = warp id).
#pragma unroll
    for (int i = 0; i < KI; i++) {
        int k0 = km * Kw + i * 16;
#pragma unroll
        for (int nt = 0; nt < 6; nt++) {
            int gate = nt >> 1;
            int jl = (nt & 1) * 8 + g;
            int n = gate * H + j0 + jl;
            const __half* p = whh + (long)n * K + k0 + tg * 2;
            int base2 = ((((km * KI + i) * 6 + nt) * 32) + lane) * 2;
            sB[base2]     = ld32h(p);
            sB[base2 + 1] = ld32h(p + 8);
        }
    }
    // Stage W_ih2 fragments once (LAYER1).
    if (LAYER == 1) {
        for (int e = w; e < 32 * 12; e += 8) {
            int ki = e / 12, nt = e % 12;
            int n = j96 + nt * 8 + g;
            const __half* p = wih2s + (long)n * 512 + ki * 16 + tg * 2;
            int base2 = ((ki * 12 + nt) * 32 + lane) * 2;
            sW2[base2]     = ld32h(p);
            sW2[base2 + 1] = ld32h(p + 8);
        }
    }

    // Per-group per-pair gate state.
    const bool active = (tid < PAIRS);
    int pb = 0, pj = 0, pjl = 0;
    float hp0[GPC], hp1[GPC];
    float2 br2 = {0, 0}, bz2 = {0, 0}, bn2 = {0, 0};
    const float* gxb[GPC];
    float2 xr2[GPC], xz2[GPC], xn2[GPC];
    if (active) {
        pb = tid >> 3;
        pjl = (tid & 7) * 2;
        pj = j0 + pjl;
        br2 = *reinterpret_cast<const float2*>(&bhh[pj]);
        bz2 = *reinterpret_cast<const float2*>(&bhh[H + pj]);
        bn2 = *reinterpret_cast<const float2*>(&bhh[2 * H + pj]);
#pragma unroll
        for (int s = 0; s < GPC; s++) {
            hp0[s] = 0.0f; hp1[s] = 0.0f;
            gxb[s] = gx + (long)(row0s[s] + pb) * TT * GA + pj;
            *reinterpret_cast<__half2*>(&d_hbuf16[0][(row0s[s] + pb) * H + pj]) = __floats2half2_rn(0.0f, 0.0f);
            xr2[s] = *reinterpret_cast<const float2*>(gxb[s]);
            xz2[s] = *reinterpret_cast<const float2*>(gxb[s] + H);
            xn2[s] = *reinterpret_cast<const float2*>(gxb[s] + 2 * H);
        }
    }

#pragma unroll
    for (int s = 0; s < GPC; s++) bar_arrive(ctrs[s]);

    for (int t = 0; t < TT; t++) {
        const int cur = t & 1, nxt = cur ^ 1;
#pragma unroll
        for (int s = 0; s < GPC; s++) {
            bar_wait(ctrs[s], (unsigned)(t + 1) * CJ);
            const __half* hA = d_hbuf16[cur] + (long)row0s[s] * H;

            // Self-stage this warp's 16 rows x K-chunk in NSPLIT commit groups.
#pragma unroll
            for (int pp = 0; pp < NSPLIT; pp++) {
                int colbase = km * Kw + pp * PARTW;
#pragma unroll
                for (int c = 0; c < ITER; c++) {
                    int idx = c * 32 + lane;
                    int r = idx / CPR, cc = idx % CPR;
                    int col = colbase + cc * 8;
                    cp16(&sH[r * STRIDE + col], hA + (long)r * H + col);
                }
                cp_commit();
            }

            float acc[6][4];
#pragma unroll
            for (int q = 0; q < 6; q++)
#pragma unroll
                for (int e = 0; e < 4; e++) acc[q][e] = 0.0f;

#pragma unroll
            for (int pp = 0; pp < NSPLIT; pp++) {
                cp_wait_dyn(NSPLIT - 1 - pp);
                __syncwarp(0xffffffffu);
#pragma unroll
                for (int i = pp * KIP; i < (pp + 1) * KIP; i++) {
                    int k0 = km * Kw + i * 16;
                    uint32_t a[4];
                    ldsm_x4(a, sH + lr * STRIDE + k0 + lc);
#pragma unroll
                    for (int nt = 0; nt < 6; nt++) {
                        int base2 = ((((km * KI + i) * 6 + nt) * 32) + lane) * 2;
                        uint2 bp = *reinterpret_cast<const uint2*>(&sB[base2]);
                        uint32_t b[2] = { bp.x, bp.y };
                        mma16816(acc[nt], a, b);
                    }
                }
            }

            // per-K-chunk partials -> SMEM: [KSPLIT][16][48]
#pragma unroll
            for (int nt = 0; nt < 6; nt++) {
                float* c = acc[nt];
                int col = nt * 8 + tg * 2;
                *reinterpret_cast<float2*>(&sRed[(km * ROWS + g) * 48 + col])     = make_float2(c[0], c[1]);
                *reinterpret_cast<float2*>(&sRed[(km * ROWS + g + 8) * 48 + col]) = make_float2(c[2], c[3]);
            }
            __syncthreads();

            // gate math.
            if (active) {
                float hr0 = br2.x, hr1 = br2.y;
                float hz0 = bz2.x, hz1 = bz2.y;
                float hn0 = bn2.x, hn1 = bn2.y;
#pragma unroll
                for (int kk = 0; kk < KSPLIT; kk++) {
                    const float* rr = &sRed[(kk * ROWS + pb) * 48];
                    float2 a0 = *reinterpret_cast<const float2*>(rr + pjl);
                    float2 a1 = *reinterpret_cast<const float2*>(rr + 16 + pjl);
                    float2 a2 = *reinterpret_cast<const float2*>(rr + 32 + pjl);
                    hr0 += a0.x; hr1 += a0.y;
                    hz0 += a1.x; hz1 += a1.y;
                    hn0 += a2.x; hn1 += a2.y;
                }
                float r0, r1, z0, z1;
                sigm2_hw(xr2[s].x + hr0, xr2[s].y + hr1, r0, r1);
                sigm2_hw(xz2[s].x + hz0, xz2[s].y + hz1, z0, z1);
                float n0 = tanh_hw(fmaf(r0, hn0, xn2[s].x));
                float n1 = tanh_hw(fmaf(r1, hn1, xn2[s].y));
                float h0 = fmaf(z0, hp0[s] - n0, n0);
                float h1 = fmaf(z1, hp1[s] - n1, n1);
                hp0[s] = h0; hp1[s] = h1;
                *reinterpret_cast<__half2*>(&d_hbuf16[nxt][(row0s[s] + pb) * H + pj]) = __floats2half2_rn(h0, h1);
                if (LAYER == 2) {
                    *reinterpret_cast<float2*>(&outp[((long)(row0s[s] + pb) * TT + t) * H + pj]) = make_float2(h0, h1);
                }
            }

            bar_arrive(ctrs[s]);

            // window work: gx2 for this group (sH stable until next phase's stage,
            // which is separated by that phase's bar_wait syncthreads).
            if (LAYER == 1 && t >= 1) {
                gx2_slice<STRIDE>(sH, sW2, gx2out, bih2, row0s[s], j96, t - 1, w, lane);
            }
            if (active && t + 1 < TT) {
                const float* p = gxb[s] + (long)(t + 1) * GA;
                xr2[s] = *reinterpret_cast<const float2*>(p);
                xz2[s] = *reinterpret_cast<const float2*>(p + H);
                xn2[s] = *reinterpret_cast<const float2*>(p + 2 * H);
            }
        }
    }

    // Tail (LAYER1): gx2(TT-1) per group.
    if (LAYER == 1) {
#pragma unroll
        for (int s = 0; s < GPC; s++) {
            bar_wait(ctrs[s], (unsigned)(TT + 1) * CJ);
            const __half* hA = d_hbuf16[TT & 1] + (long)row0s[s] * H;
#pragma unroll
            for (int pp = 0; pp < NSPLIT; pp++) {
                int colbase = km * Kw + pp * PARTW;
#pragma unroll
                for (int c = 0; c < ITER; c++) {
                    int idx = c * 32 + lane;
                    int r = idx / CPR, cc = idx % CPR;
                    int col = colbase + cc * 8;
                    cp16(&sH[r * STRIDE + col], hA + (long)r * H + col);
                }
            }
            cp_commit();
            cp_wait0();
            __syncthreads();
            gx2_slice<STRIDE>(sH, sW2, gx2out, bih2, row0s[s], j96, TT - 1, w, lane);
            __syncthreads();
        }
    }
}

// ---------------- launch ----------------
extern "C" void kernel_launch(void* const* d_in, const int* in_sizes, int n_in,
                              void* d_out, int out_size) {
    const float* x    = (const float*)d_in[0];
    const float* wih1 = (const float*)d_in[1];
    const float* whh1 = (const float*)d_in[2];
    const float* bih1 = (const float*)d_in[3];
    const float* bhh1 = (const float*)d_in[4];
    const float* wih2 = (const float*)d_in[5];
    const float* whh2 = (const float*)d_in[6];
    const float* bih2 = (const float*)d_in[7];
    const float* bhh2 = (const float*)d_in[8];
    float* out = (float*)d_out;

    void *p_xh, *p_wih1, *p_whh1, *p_wih2, *p_whh2, *p_gx1, *p_gx2, *p_bar1, *p_bar2;
    cudaGetSymbolAddress(&p_xh, d_xh);
    cudaGetSymbolAddress(&p_wih1, d_wih1);
    cudaGetSymbolAddress(&p_whh1, d_whh1);
    cudaGetSymbolAddress(&p_wih2, d_wih2);
    cudaGetSymbolAddress(&p_whh2, d_whh2);
    cudaGetSymbolAddress(&p_gx1, d_gx1);
    cudaGetSymbolAddress(&p_gx2, d_gx2);
    cudaGetSymbolAddress(&p_bar1, d_bar1);
    cudaGetSymbolAddress(&p_bar2, d_bar2);

    // rec1 (H=512, KSPLIT=8, KI=4): sH 16*520*2=16640 + sB 8*4*6*64*4=49152
    //   + sRed 8*16*48*4=24576 + sW2 32*12*64*4=98304 = 188672
    const int SMEM1 = 16 * (512 + 8) * 2 + 8 * 4 * 6 * 64 * 4 + 8 * 16 * 48 * 4 + 32 * 12 * 64 * 4;
    // rec2 (H=1024, KSPLIT=8, KI=8): sH 16*1032*2=33024 + sB 8*8*6*64*4=98304
    //   + sRed 24576 = 155904
    const int SMEM2 = 16 * (1024 + 8) * 2 + 8 * 8 * 6 * 64 * 4 + 8 * 16 * 48 * 4;
    cudaFuncSetAttribute((const void*)rec_kernel<512, 1, 8, 4, 2, 2>,
                         cudaFuncAttributeMaxDynamicSharedMemorySize, SMEM1);
    cudaFuncSetAttribute((const void*)rec_kernel<1024, 2, 8, 4, 2, 2>,
                         cudaFuncAttributeMaxDynamicSharedMemorySize, SMEM2);

    prep_kernel<<<2048, 256>>>(x, wih1, whh1, wih2, whh2);

    {   // gx1 = x @ W_ih1^T + b_ih1 : [16384,1536], K=1024
        dim3 grid(1536 / 128, 16384 / 128);
        gemm_tn_kernel<<<grid, 256>>>((const __half*)p_xh, (const __half*)p_wih1,
                                      bih1, (float*)p_gx1, 16384, 1536, 1024);
    }

    // layer-1: 4 groups of 16 rows, 2 groups/CTA -> 2 pairs x 32 col-CTAs = 64 CTAs
    rec_kernel<512, 1, 8, 4, 2, 2><<<64, 256, SMEM1>>>(
        (const float*)p_gx1, (const __half*)p_whh1, bhh1, nullptr, (unsigned int*)p_bar1,
        (const __half*)p_wih2, bih2, (float*)p_gx2);

    // layer-2: 4 groups of 16 rows, 2 groups/CTA -> 2 pairs x 64 col-CTAs = 128 CTAs
    rec_kernel<1024, 2, 8, 4, 2, 2><<<128, 256, SMEM2>>>(
        (const float*)p_gx2, (const __half*)p_whh2, bhh2, out, (unsigned int*)p_bar2,
        nullptr, nullptr, nullptr);
}

// round 17
// speedup vs baseline: 1.6821x; 1.6821x over previous
#include <cuda_runtime.h>
#include <cuda_fp16.h>
#include <math.h>
#include <stdint.h>

#define BB 64
#define TT 256
#define IIN 1024
#define HHID 512

// ---------------- device scratch (static: no allocations allowed) ----------------
__device__ __half d_xh[16384u * 1024u];
__device__ __half d_wih1[1536u * 1024u];
__device__ __half d_whh1[1536u * 512u];
__device__ __half d_wih2[3072u * 512u];
__device__ __half d_whh2[3072u * 1024u];
__device__ float  d_gx1[16384u * 1536u];
__device__ float  d_gx2[16384u * 3072u];
__device__ __half d_hbuf16[2][64 * 1024];
// Barrier counters: one padded 128B line per group.
__device__ unsigned int d_bar1[4 * 32];
__device__ unsigned int d_bar2[2 * 32];

// ---------------- helpers ----------------
__device__ __forceinline__ uint32_t ld32h(const __half* p) {
    return *reinterpret_cast<const uint32_t*>(p);
}

__device__ __forceinline__ void mma16816(float* c, const uint32_t* a, const uint32_t* b) {
    asm volatile(
        "mma.sync.aligned.m16n8k16.row.col.f32.f16.f16.f32 "
        "{%0,%1,%2,%3}, {%4,%5,%6,%7}, {%8,%9}, {%0,%1,%2,%3};\n"
        : "+f"(c[0]), "+f"(c[1]), "+f"(c[2]), "+f"(c[3])
        : "r"(a[0]), "r"(a[1]), "r"(a[2]), "r"(a[3]), "r"(b[0]), "r"(b[1]));
}

__device__ __forceinline__ void ldsm_x4(uint32_t* r, const __half* p) {
    unsigned sa = (unsigned)__cvta_generic_to_shared(p);
    asm volatile("ldmatrix.sync.aligned.m8n8.x4.shared.b16 {%0,%1,%2,%3}, [%4];\n"
                 : "=r"(r[0]), "=r"(r[1]), "=r"(r[2]), "=r"(r[3]) : "r"(sa));
}

__device__ __forceinline__ uint32_t relu_h2(uint32_t x) {
    uint32_t r;
    asm("max.f16x2 %0, %1, %2;\n" : "=r"(r) : "r"(x), "r"(0u));
    return r;
}

__device__ __forceinline__ float tanh_hw(float x) {
    float y;
    asm("tanh.approx.f32 %0, %1;\n" : "=f"(y) : "f"(x));
    return y;
}
__device__ __forceinline__ void sigm2_hw(float x0, float x1, float& s0, float& s1) {
    __half2 hin = __floats2half2_rn(0.5f * x0, 0.5f * x1);
    uint32_t uin = *reinterpret_cast<uint32_t*>(&hin);
    uint32_t uout;
    asm("tanh.approx.f16x2 %0, %1;\n" : "=r"(uout) : "r"(uin));
    __half2 hout = *reinterpret_cast<__half2*>(&uout);
    float2 t = __half22float2(hout);
    s0 = fmaf(t.x, 0.5f, 0.5f);
    s1 = fmaf(t.y, 0.5f, 0.5f);
}

__device__ __forceinline__ void cp16(void* s, const void* g) {
    unsigned sa = (unsigned)__cvta_generic_to_shared(s);
    asm volatile("cp.async.cg.shared.global [%0], [%1], 16;\n" :: "r"(sa), "l"(g));
}
__device__ __forceinline__ void cp_commit() { asm volatile("cp.async.commit_group;\n"); }
__device__ __forceinline__ void cp_wait0()  { asm volatile("cp.async.wait_group 0;\n"); }
__device__ __forceinline__ void cp_wait_dyn(int n) {
    switch (n) {
        case 0: asm volatile("cp.async.wait_group 0;\n"); break;
        case 1: asm volatile("cp.async.wait_group 1;\n"); break;
        case 2: asm volatile("cp.async.wait_group 2;\n"); break;
        default: asm volatile("cp.async.wait_group 3;\n"); break;
    }
}

// Split grid barrier (single padded counter per group).
__device__ __forceinline__ void bar_arrive(unsigned int* ctr) {
    __syncthreads();
    if (threadIdx.x == 0) {
        asm volatile("red.release.gpu.global.add.u32 [%0], 1;\n" :: "l"(ctr) : "memory");
    }
}
__device__ __forceinline__ void bar_wait(unsigned int* ctr, unsigned int target) {
    if (threadIdx.x == 0) {
        unsigned int v;
        do {
            asm volatile("ld.acquire.gpu.global.u32 %0, [%1];\n" : "=r"(v) : "l"(ctr) : "memory");
        } while (v < target);
    }
    __syncthreads();
}

// ---------------- prep (vectorized float4 -> half2) ----------------
__device__ __forceinline__ void cvt4(__half2* dst, const float4* src, long n4, long idx, long stride) {
    for (long i = idx; i < n4; i += stride) {
        float4 v = src[i];
        dst[2 * i]     = __floats2half2_rn(v.x, v.y);
        dst[2 * i + 1] = __floats2half2_rn(v.z, v.w);
    }
}
__global__ void prep_kernel(const float* __restrict__ x,
                            const float* __restrict__ wih1, const float* __restrict__ whh1,
                            const float* __restrict__ wih2, const float* __restrict__ whh2) {
    long idx = (long)blockIdx.x * blockDim.x + threadIdx.x;
    long stride = (long)gridDim.x * blockDim.x;
    if (idx < 4 * 32) d_bar1[idx] = 0u;
    if (idx < 2 * 32) d_bar2[idx] = 0u;
    cvt4((__half2*)d_xh,   (const float4*)x,    16384L * 1024L / 4, idx, stride);
    cvt4((__half2*)d_wih1, (const float4*)wih1, 1536L * 1024L / 4,  idx, stride);
    cvt4((__half2*)d_whh1, (const float4*)whh1, 1536L * 512L / 4,   idx, stride);
    cvt4((__half2*)d_wih2, (const float4*)wih2, 3072L * 512L / 4,   idx, stride);
    cvt4((__half2*)d_whh2, (const float4*)whh2, 3072L * 1024L / 4,  idx, stride);
}

// ---------------- 3-stage pipelined SMEM GEMM, A+B frags via ldmatrix ----------------
// No empty commit groups: wait depth = min(KT-1-kt, 2).
#define SSTR 40
#define GSTG 3
__global__ __launch_bounds__(256) void gemm_tn_kernel(
        const __half* __restrict__ A, const __half* __restrict__ W,
        const float* __restrict__ bias, float* __restrict__ C,
        int M, int N, int K) {
    extern __shared__ __half gsm[];
    __half* sA = gsm;                       // [GSTG][128*SSTR]
    __half* sB = gsm + GSTG * 128 * SSTR;

    const int bn = blockIdx.x * 128;
    const int bm = blockIdx.y * 128;
    const int tid = threadIdx.x;
    const int w = tid >> 5, lane = tid & 31;
    const int g = lane >> 2, tg = lane & 3;
    const int wm = (w >> 2) * 64;
    const int wn = (w & 3) * 32;
    const int lr = lane & 15, lc = (lane >> 4) << 3;

    float acc[4][4][4];
#pragma unroll
    for (int mt = 0; mt < 4; mt++)
#pragma unroll
        for (int nt = 0; nt < 4; nt++)
#pragma unroll
            for (int e = 0; e < 4; e++) acc[mt][nt][e] = 0.0f;

    const int KT = K >> 5;
    // prologue: commit tiles 0,1
#pragma unroll
    for (int s = 0; s < 2; s++) {
        int k0 = s << 5;
#pragma unroll
        for (int c = 0; c < 2; c++) {
            int chunk = tid + c * 256;
            int r = chunk >> 2, cc = chunk & 3;
            cp16(&sA[(s * 128 + r) * SSTR + cc * 8], A + (long)(bm + r) * K + k0 + cc * 8);
            cp16(&sB[(s * 128 + r) * SSTR + cc * 8], W + (long)(bn + r) * K + k0 + cc * 8);
        }
        cp_commit();
    }

    for (int kt = 0; kt < KT; kt++) {
        __syncthreads();   // everyone done computing tile kt-1 (its buffer = (kt+2)%3)
        if (kt + 2 < KT) {
            int k0 = (kt + 2) << 5;
            int sb = (kt + 2) % GSTG;
#pragma unroll
            for (int c = 0; c < 2; c++) {
                int chunk = tid + c * 256;
                int r = chunk >> 2, cc = chunk & 3;
                cp16(&sA[(sb * 128 + r) * SSTR + cc * 8], A + (long)(bm + r) * K + k0 + cc * 8);
                cp16(&sB[(sb * 128 + r) * SSTR + cc * 8], W + (long)(bn + r) * K + k0 + cc * 8);
            }
            cp_commit();
        }
        int wn_depth = KT - 1 - kt;
        cp_wait_dyn(wn_depth < 2 ? wn_depth : 2);
        __syncthreads();

        const __half* a_s = sA + (kt % GSTG) * 128 * SSTR;
        const __half* b_s = sB + (kt % GSTG) * 128 * SSTR;
#pragma unroll
        for (int ks = 0; ks < 2; ks++) {
            const int kk = ks * 16;
            uint32_t af[4][4];
#pragma unroll
            for (int mt = 0; mt < 4; mt++) {
                ldsm_x4(af[mt], a_s + (wm + mt * 16 + lr) * SSTR + kk + lc);
            }
            uint32_t bm4[2][4];
#pragma unroll
            for (int h = 0; h < 2; h++) {
                ldsm_x4(bm4[h], b_s + (wn + h * 16 + lr) * SSTR + kk + lc);
            }
            uint32_t bf[4][2];
#pragma unroll
            for (int h = 0; h < 2; h++) {
                bf[h * 2][0]     = bm4[h][0];
                bf[h * 2][1]     = bm4[h][2];
                bf[h * 2 + 1][0] = bm4[h][1];
                bf[h * 2 + 1][1] = bm4[h][3];
            }
#pragma unroll
            for (int mt = 0; mt < 4; mt++)
#pragma unroll
                for (int nt = 0; nt < 4; nt++) mma16816(acc[mt][nt], af[mt], bf[nt]);
        }
    }

#pragma unroll
    for (int mt = 0; mt < 4; mt++) {
        int row0 = bm + wm + mt * 16 + g;
#pragma unroll
        for (int nt = 0; nt < 4; nt++) {
            int col = bn + wn + nt * 8 + tg * 2;
            float b0 = bias[col], b1 = bias[col + 1];
            float2 v0 = make_float2(acc[mt][nt][0] + b0, acc[mt][nt][1] + b1);
            float2 v1 = make_float2(acc[mt][nt][2] + b0, acc[mt][nt][3] + b1);
            *reinterpret_cast<float2*>(&C[(long)row0 * N + col])       = v0;
            *reinterpret_cast<float2*>(&C[(long)(row0 + 8) * N + col]) = v1;
        }
    }
}

// gx2 slice from sH (raw h1 in fp16; relu applied in-register).
template <int STRIDE>
__device__ __forceinline__ void gx2_slice(const __half* sH, const uint32_t* sW2,
                                          float* gx2out, const float* bih2,
                                          int row0, int j96, int t, int w, int lane) {
    const int g = lane >> 2, tg = lane & 3;
    const int lr = lane & 15, lc = (lane >> 4) << 3;
    float acc2[2][4];
#pragma unroll
    for (int rep = 0; rep < 2; rep++)
#pragma unroll
        for (int e = 0; e < 4; e++) acc2[rep][e] = 0.0f;
#pragma unroll
    for (int ki = 0; ki < 32; ki++) {
        uint32_t a[4];
        ldsm_x4(a, sH + lr * STRIDE + ki * 16 + lc);
#pragma unroll
        for (int q = 0; q < 4; q++) a[q] = relu_h2(a[q]);
#pragma unroll
        for (int rep = 0; rep < 2; rep++) {
            if (rep == 0 || w < 4) {
                int nt = w + rep * 8;
                int base2 = ((ki * 12 + nt) * 32 + lane) * 2;
                uint2 bp = *reinterpret_cast<const uint2*>(&sW2[base2]);
                uint32_t b[2] = { bp.x, bp.y };
                mma16816(acc2[rep], a, b);
            }
        }
    }
#pragma unroll
    for (int rep = 0; rep < 2; rep++) {
        if (rep == 0 || w < 4) {
            int nt = w + rep * 8;
            int col = j96 + nt * 8 + tg * 2;
            float bi0 = bih2[col], bi1 = bih2[col + 1];
            long o0 = ((long)(row0 + g) * TT + t) * 3072 + col;
            long o1 = ((long)(row0 + g + 8) * TT + t) * 3072 + col;
            *reinterpret_cast<float2*>(&gx2out[o0]) = make_float2(acc2[rep][0] + bi0, acc2[rep][1] + bi1);
            *reinterpret_cast<float2*>(&gx2out[o1]) = make_float2(acc2[rep][2] + bi0, acc2[rep][3] + bi1);
        }
    }
}

// ---------------- persistent GRU recurrence (R15 proven structure) ----------------
template <int H, int LAYER, int ROWS, int KSPLIT, int GROUPS, int NSPLIT>
__global__ __launch_bounds__(256) void rec_kernel(
        const float* __restrict__ gx, const __half* __restrict__ whh,
        const float* __restrict__ bhh, float* __restrict__ outp,
        unsigned int* __restrict__ barctr,
        const __half* __restrict__ wih2s, const float* __restrict__ bih2,
        float* __restrict__ gx2out) {
    constexpr int K = H;
    constexpr int Kw = K / KSPLIT;
    constexpr int KI = Kw / 16;
    constexpr int CJ = H / 16;
    constexpr int GA = 3 * H;
    constexpr int STRIDE = H + 8;
    constexpr int PAIRS = ROWS * 8;
    constexpr int PARTW = Kw / NSPLIT;
    constexpr int CPR = PARTW / 8;
    constexpr int ITER = (16 * CPR) / 32;
    constexpr int KIP = KI / NSPLIT;

    extern __shared__ unsigned char smem[];
    __half*   sH   = reinterpret_cast<__half*>(smem);
    uint32_t* sB   = reinterpret_cast<uint32_t*>(smem + (size_t)ROWS * STRIDE * 2);
    float*    sRed = reinterpret_cast<float*>(smem + (size_t)ROWS * STRIDE * 2 + (size_t)KSPLIT * KI * 6 * 64 * 4);
    uint32_t* sW2  = reinterpret_cast<uint32_t*>(smem + (size_t)ROWS * STRIDE * 2 + (size_t)KSPLIT * KI * 6 * 64 * 4
                                                 + (size_t)KSPLIT * ROWS * 48 * 4);

    const int tid = threadIdx.x;
    const int w = tid >> 5, lane = tid & 31;
    const int km = w % KSPLIT, mh = w / KSPLIT;
    const int g = lane >> 2, tg = lane & 3;
    const int grp = blockIdx.x % GROUPS;
    const int cidx = blockIdx.x / GROUPS;
    const int j0 = cidx * 16;
    const int j96 = cidx * 96;
    const int row0 = grp * ROWS;
    const int mrow = mh * 16;
    const int lr = lane & 15, lc = (lane >> 4) << 3;
    unsigned int* ctr = barctr + grp * 32;

    // Stage W_hh fragments once.
    if (mh == 0) {
#pragma unroll
        for (int i = 0; i < KI; i++) {
            int k0 = km * Kw + i * 16;
#pragma unroll
            for (int nt = 0; nt < 6; nt++) {
                int gate = nt >> 1;
                int jl = (nt & 1) * 8 + g;
                int n = gate * H + j0 + jl;
                const __half* p = whh + (long)n * K + k0 + tg * 2;
                int base2 = ((((km * KI + i) * 6 + nt) * 32) + lane) * 2;
                sB[base2]     = ld32h(p);
                sB[base2 + 1] = ld32h(p + 8);
            }
        }
    }
    // Stage W_ih2 fragments once (LAYER1).
    if (LAYER == 1) {
        for (int e = w; e < 32 * 12; e += 8) {
            int ki = e / 12, nt = e % 12;
            int n = j96 + nt * 8 + g;
            const __half* p = wih2s + (long)n * 512 + ki * 16 + tg * 2;
            int base2 = ((ki * 12 + nt) * 32 + lane) * 2;
            sW2[base2]     = ld32h(p);
            sW2[base2 + 1] = ld32h(p + 8);
        }
    }

    // Per-pair gate state (active threads: tid < PAIRS).
    const bool active = (tid < PAIRS);
    int pb = 0, pj = 0, pjl = 0;
    float hp0 = 0.0f, hp1 = 0.0f;
    float2 br2 = {0, 0}, bz2 = {0, 0}, bn2 = {0, 0};
    const float* gxb = nullptr;
    float2 xr2 = {0, 0}, xz2 = {0, 0}, xn2 = {0, 0};
    if (active) {
        pb = tid >> 3;
        pjl = (tid & 7) * 2;
        pj = j0 + pjl;
        br2 = *reinterpret_cast<const float2*>(&bhh[pj]);
        bz2 = *reinterpret_cast<const float2*>(&bhh[H + pj]);
        bn2 = *reinterpret_cast<const float2*>(&bhh[2 * H + pj]);
        gxb = gx + (long)(row0 + pb) * TT * GA + pj;
        *reinterpret_cast<__half2*>(&d_hbuf16[0][(row0 + pb) * H + pj]) = __floats2half2_rn(0.0f, 0.0f);
        xr2 = *reinterpret_cast<const float2*>(gxb);
        xz2 = *reinterpret_cast<const float2*>(gxb + H);
        xn2 = *reinterpret_cast<const float2*>(gxb + 2 * H);
    }

    unsigned int ibar = 0;
    bar_arrive(ctr);
    bar_wait(ctr, (++ibar) * CJ);

    for (int t = 0; t < TT; t++) {
        const int cur = t & 1, nxt = cur ^ 1;
        const __half* hA = d_hbuf16[cur] + (long)row0 * H;

        // Self-stage this warp's 16 rows x K-chunk in NSPLIT commit groups.
#pragma unroll
        for (int pp = 0; pp < NSPLIT; pp++) {
            int colbase = km * Kw + pp * PARTW;
#pragma unroll
            for (int c = 0; c < ITER; c++) {
                int idx = c * 32 + lane;
                int r = idx / CPR, cc = idx % CPR;
                int row = mrow + r, col = colbase + cc * 8;
                cp16(&sH[row * STRIDE + col], hA + (long)row * H + col);
            }
            cp_commit();
        }

        float acc[6][4];
#pragma unroll
        for (int q = 0; q < 6; q++)
#pragma unroll
            for (int e = 0; e < 4; e++) acc[q][e] = 0.0f;

#pragma unroll
        for (int pp = 0; pp < NSPLIT; pp++) {
            cp_wait_dyn(NSPLIT - 1 - pp);
            __syncwarp(0xffffffffu);
#pragma unroll
            for (int i = pp * KIP; i < (pp + 1) * KIP; i++) {
                int k0 = km * Kw + i * 16;
                uint32_t a[4];
                ldsm_x4(a, sH + (mrow + lr) * STRIDE + k0 + lc);
#pragma unroll
                for (int nt = 0; nt < 6; nt++) {
                    int base2 = ((((km * KI + i) * 6 + nt) * 32) + lane) * 2;
                    uint2 bp = *reinterpret_cast<const uint2*>(&sB[base2]);
                    uint32_t b[2] = { bp.x, bp.y };
                    mma16816(acc[nt], a, b);
                }
            }
        }

        // per-K-chunk partials -> SMEM: [KSPLIT][ROWS][48]
#pragma unroll
        for (int nt = 0; nt < 6; nt++) {
            float* c = acc[nt];
            int col = nt * 8 + tg * 2;
            int row = mrow + g;
            *reinterpret_cast<float2*>(&sRed[(km * ROWS + row) * 48 + col])     = make_float2(c[0], c[1]);
            *reinterpret_cast<float2*>(&sRed[(km * ROWS + row + 8) * 48 + col]) = make_float2(c[2], c[3]);
        }
        __syncthreads();

        // gate math (paired columns; r/z via one f16x2 HW tanh each, n in fp32).
        if (active) {
            float hr0 = br2.x, hr1 = br2.y;
            float hz0 = bz2.x, hz1 = bz2.y;
            float hn0 = bn2.x, hn1 = bn2.y;
#pragma unroll
            for (int kk = 0; kk < KSPLIT; kk++) {
                const float* rr = &sRed[(kk * ROWS + pb) * 48];
                float2 a0 = *reinterpret_cast<const float2*>(rr + pjl);
                float2 a1 = *reinterpret_cast<const float2*>(rr + 16 + pjl);
                float2 a2 = *reinterpret_cast<const float2*>(rr + 32 + pjl);
                hr0 += a0.x; hr1 += a0.y;
                hz0 += a1.x; hz1 += a1.y;
                hn0 += a2.x; hn1 += a2.y;
            }
            float r0, r1, z0, z1;
            sigm2_hw(xr2.x + hr0, xr2.y + hr1, r0, r1);
            sigm2_hw(xz2.x + hz0, xz2.y + hz1, z0, z1);
            float n0 = tanh_hw(fmaf(r0, hn0, xn2.x));
            float n1 = tanh_hw(fmaf(r1, hn1, xn2.y));
            float h0 = fmaf(z0, hp0 - n0, n0);
            float h1 = fmaf(z1, hp1 - n1, n1);
            hp0 = h0; hp1 = h1;
            *reinterpret_cast<__half2*>(&d_hbuf16[nxt][(row0 + pb) * H + pj]) = __floats2half2_rn(h0, h1);
            if (LAYER == 2) {
                *reinterpret_cast<float2*>(&outp[((long)(row0 + pb) * TT + t) * H + pj]) = make_float2(h0, h1);
            }
        }

        // Arrive, then fill the barrier-wait window with useful work.
        bar_arrive(ctr);
        ++ibar;

        if (LAYER == 1 && t >= 1) {
            gx2_slice<STRIDE>(sH, sW2, gx2out, bih2, row0, j96, t - 1, w, lane);
        }
        if (active && t + 1 < TT) {
            const float* p = gxb + (long)(t + 1) * GA;
            xr2 = *reinterpret_cast<const float2*>(p);
            xz2 = *reinterpret_cast<const float2*>(p + H);
            xn2 = *reinterpret_cast<const float2*>(p + 2 * H);
        }
        bar_wait(ctr, ibar * CJ);
    }

    // Tail (LAYER1): gx2(TT-1) from h1(TT-1), now group-visible.
    if (LAYER == 1) {
        const __half* hA = d_hbuf16[TT & 1] + (long)row0 * H;
#pragma unroll
        for (int pp = 0; pp < NSPLIT; pp++) {
            int colbase = km * Kw + pp * PARTW;
#pragma unroll
            for (int c = 0; c < ITER; c++) {
                int idx = c * 32 + lane;
                int r = idx / CPR, cc = idx % CPR;
                int row = mrow + r, col = colbase + cc * 8;
                cp16(&sH[row * STRIDE + col], hA + (long)row * H + col);
            }
        }
        cp_commit();
        cp_wait0();
        __syncthreads();
        gx2_slice<STRIDE>(sH, sW2, gx2out, bih2, row0, j96, TT - 1, w, lane);
    }
}

// ---------------- launch ----------------
extern "C" void kernel_launch(void* const* d_in, const int* in_sizes, int n_in,
                              void* d_out, int out_size) {
    const float* x    = (const float*)d_in[0];
    const float* wih1 = (const float*)d_in[1];
    const float* whh1 = (const float*)d_in[2];
    const float* bih1 = (const float*)d_in[3];
    const float* bhh1 = (const float*)d_in[4];
    const float* wih2 = (const float*)d_in[5];
    const float* whh2 = (const float*)d_in[6];
    const float* bih2 = (const float*)d_in[7];
    const float* bhh2 = (const float*)d_in[8];
    float* out = (float*)d_out;

    void *p_xh, *p_wih1, *p_whh1, *p_wih2, *p_whh2, *p_gx1, *p_gx2, *p_bar1, *p_bar2;
    cudaGetSymbolAddress(&p_xh, d_xh);
    cudaGetSymbolAddress(&p_wih1, d_wih1);
    cudaGetSymbolAddress(&p_whh1, d_whh1);
    cudaGetSymbolAddress(&p_wih2, d_wih2);
    cudaGetSymbolAddress(&p_whh2, d_whh2);
    cudaGetSymbolAddress(&p_gx1, d_gx1);
    cudaGetSymbolAddress(&p_gx2, d_gx2);
    cudaGetSymbolAddress(&p_bar1, d_bar1);
    cudaGetSymbolAddress(&p_bar2, d_bar2);

    const int GEMM_SMEM = GSTG * 128 * SSTR * 2 * 2;   // 61440
    cudaFuncSetAttribute(gemm_tn_kernel, cudaFuncAttributeMaxDynamicSharedMemorySize, GEMM_SMEM);

    // rec1: sH 16*520*2 + sB 8*4*6*64*4 + sRed 8*16*48*4 + sW2 32*12*64*4 = 188672
    const int SMEM1 = 16 * (512 + 8) * 2 + 8 * 4 * 6 * 64 * 4 + 8 * 16 * 48 * 4 + 32 * 12 * 64 * 4;
    // rec2: sH 32*1032*2 + sB 4*16*6*64*4 + sRed 4*32*48*4 = 188928
    const int SMEM2 = 32 * (1024 + 8) * 2 + 4 * 16 * 6 * 64 * 4 + 4 * 32 * 48 * 4;
    cudaFuncSetAttribute((const void*)rec_kernel<512, 1, 16, 8, 4, 2>,
                         cudaFuncAttributeMaxDynamicSharedMemorySize, SMEM1);
    cudaFuncSetAttribute((const void*)rec_kernel<1024, 2, 32, 4, 2, 4>,
                         cudaFuncAttributeMaxDynamicSharedMemorySize, SMEM2);

    prep_kernel<<<2048, 256>>>(x, wih1, whh1, wih2, whh2);

    {   // gx1 = x @ W_ih1^T + b_ih1 : [16384,1536], K=1024
        dim3 grid(1536 / 128, 16384 / 128);
        gemm_tn_kernel<<<grid, 256, GEMM_SMEM>>>((const __half*)p_xh, (const __half*)p_wih1,
                                                 bih1, (float*)p_gx1, 16384, 1536, 1024);
    }

    // layer-1 recurrence + window-fused gx2: 4 groups x 32 column-CTAs = 128 CTAs
    rec_kernel<512, 1, 16, 8, 4, 2><<<128, 256, SMEM1>>>(
        (const float*)p_gx1, (const __half*)p_whh1, bhh1, nullptr, (unsigned int*)p_bar1,
        (const __half*)p_wih2, bih2, (float*)p_gx2);

    // layer-2 recurrence: 2 groups x 64 column-CTAs = 128 CTAs
    rec_kernel<1024, 2, 32, 4, 2, 4><<<128, 256, SMEM2>>>(
        (const float*)p_gx2, (const __half*)p_whh2, bhh2, out, (unsigned int*)p_bar2,
        nullptr, nullptr, nullptr);
}